// round 12
// baseline (speedup 1.0000x reference)
#include <cuda_runtime.h>
#include <cuda_bf16.h>
#include <math.h>
#include <stdint.h>

#define Bn   2
#define Tn   2048
#define Cn   768
#define Hn   12
#define HDn  64
#define QKVn 2304
#define SCALE 0.125f   // 1/sqrt(64)
#define NSEG 32        // cumsum segments (64 rows each)

// -------- device scratch (no allocations allowed) --------
__device__ float g_ff  [Bn * Tn * Tn];       // S, then exclusive cumsum
__device__ float g_part[Bn * NSEG * Tn];     // cumsum segment partials
__device__ __nv_bfloat16 g_xh [Bn*Tn*Cn], g_xl [Bn*Tn*Cn];
__device__ __nv_bfloat16 g_wah[QKVn*Cn],  g_wal[QKVn*Cn];
__device__ __nv_bfloat16 g_wph[Cn*Cn],    g_wpl[Cn*Cn];
__device__ __nv_bfloat16 g_qh [Bn*Tn*Cn], g_ql [Bn*Tn*Cn];  // raw q (attn)
__device__ __nv_bfloat16 g_qsh[Bn*Tn*Cn], g_qsl[Bn*Tn*Cn];  // sel_w-scaled q
__device__ __nv_bfloat16 g_kh [Bn*Tn*Cn], g_kl [Bn*Tn*Cn];
__device__ __nv_bfloat16 g_vh [Bn*Tn*Cn], g_vl [Bn*Tn*Cn];
__device__ __nv_bfloat16 g_yh [Bn*Tn*Cn], g_yl [Bn*Tn*Cn];

// ======================= PTX helpers (compute_103-safe) ====================
__device__ __forceinline__ uint32_t smem_u32(const void* p) {
    uint32_t a;
    asm("{ .reg .u64 t; cvta.to.shared.u64 t, %1; cvt.u32.u64 %0, t; }"
        : "=r"(a) : "l"(p));
    return a;
}
__device__ __forceinline__ void ldsm4(uint32_t* r, uint32_t addr) {
    asm volatile("ldmatrix.sync.aligned.m8n8.x4.shared.b16 {%0,%1,%2,%3}, [%4];"
                 : "=r"(r[0]), "=r"(r[1]), "=r"(r[2]), "=r"(r[3]) : "r"(addr));
}
__device__ __forceinline__ void ldsm4t(uint32_t* r, uint32_t addr) {
    asm volatile("ldmatrix.sync.aligned.m8n8.x4.trans.shared.b16 {%0,%1,%2,%3}, [%4];"
                 : "=r"(r[0]), "=r"(r[1]), "=r"(r[2]), "=r"(r[3]) : "r"(addr));
}
__device__ __forceinline__ void mma16816(float* c, const uint32_t* a, const uint32_t* b) {
    asm volatile(
        "mma.sync.aligned.m16n8k16.row.col.f32.bf16.bf16.f32 "
        "{%0,%1,%2,%3}, {%4,%5,%6,%7}, {%8,%9}, {%0,%1,%2,%3};"
        : "+f"(c[0]), "+f"(c[1]), "+f"(c[2]), "+f"(c[3])
        : "r"(a[0]), "r"(a[1]), "r"(a[2]), "r"(a[3]), "r"(b[0]), "r"(b[1]));
}
__device__ __forceinline__ void cpasync16(uint32_t dst, const void* src) {
    asm volatile("cp.async.cg.shared.global [%0], [%1], 16;" :: "r"(dst), "l"(src));
}
// pack (v0, v1) into hi bf16x2 + lo (residual) bf16x2
__device__ __forceinline__ void split2(float v0, float v1,
                                       __nv_bfloat162& hh, __nv_bfloat162& ll) {
    hh.x = __float2bfloat16(v0);
    hh.y = __float2bfloat16(v1);
    ll.x = __float2bfloat16(v0 - __bfloat162float(hh.x));
    ll.y = __float2bfloat16(v1 - __bfloat162float(hh.y));
}

// ============================================================================
// Fused bf16 split of all three fp32 inputs (x, w_attn, w_proj) -> hi/lo
// ============================================================================
#define N_X  (Bn * Tn * Cn)
#define N_WA (QKVn * Cn)
#define N_WP (Cn * Cn)

__global__ void split_all(const float* __restrict__ x,
                          const float* __restrict__ wa,
                          const float* __restrict__ wp)
{
    const int i = blockIdx.x * 256 + threadIdx.x;
    float v; __nv_bfloat16* hd; __nv_bfloat16* ld; int ix;
    if (i < N_X) {
        v = x[i]; hd = g_xh; ld = g_xl; ix = i;
    } else if (i < N_X + N_WA) {
        ix = i - N_X; v = wa[ix]; hd = g_wah; ld = g_wal;
    } else {
        ix = i - N_X - N_WA; v = wp[ix]; hd = g_wph; ld = g_wpl;
    }
    const __nv_bfloat16 hh = __float2bfloat16(v);
    hd[ix] = hh;
    ld[ix] = __float2bfloat16(v - __bfloat162float(hh));
}

// ============================================================================
// bf16x3 tensor-core GEMM (HMMA): C[m,n]=sum_k A[m,k]*B[n,k]
// AhBh+AhBl+AlBh, fp32 accum. 128x128 block, BK=16, 8 warps.
// 3-stage cp.async pipeline (dynamic smem, 72KB), one barrier per k-iter.
// __launch_bounds__(256,2): regs<=128 -> 2 CTAs/SM.
// MODE 0 qkv (bias + split-scatter q/qs/k/v) / 1 selection-S / 2 proj.
// ============================================================================
#define TILEB 6144          // 128 rows * 48 bytes
#define STAGEB (4 * TILEB)  // Ah, Al, Bh, Bl
#define GEMM_SMEM (3 * STAGEB)  // 73728

template <int MODE>
__global__ void __launch_bounds__(256, 2)
gemm_mma(const __nv_bfloat16* __restrict__ Ah, const __nv_bfloat16* __restrict__ Al,
         const __nv_bfloat16* __restrict__ Bh, const __nv_bfloat16* __restrict__ Bl,
         int lda, int ldb, long sA, long sB,
         const float* __restrict__ bias, const float* __restrict__ selw,
         float* __restrict__ Cout)
{
    const int i0 = blockIdx.y * 128, j0 = blockIdx.x * 128, bz = blockIdx.z;
    if (MODE == 1 && j0 > i0) return;        // strictly-upper tiles: zero, never read
    Ah += (long)bz * sA; Al += (long)bz * sA;
    Bh += (long)bz * sB; Bl += (long)bz * sB;

    extern __shared__ __align__(128) char sm[];
    const uint32_t sb = smem_u32(sm);

    const int tid = threadIdx.x;
    const int lane = tid & 31, wid = tid >> 5;
    const int wm = (wid & 1) * 64, wn = (wid >> 1) * 32;

    const int lrow = tid >> 1, lhalf = tid & 1;
    const __nv_bfloat16* srcs[4] = {
        Ah + (long)(i0 + lrow) * lda + lhalf * 8,
        Al + (long)(i0 + lrow) * lda + lhalf * 8,
        Bh + (long)(j0 + lrow) * ldb + lhalf * 8,
        Bl + (long)(j0 + lrow) * ldb + lhalf * 8 };
    const uint32_t dstb = sb + lrow * 48 + lhalf * 16;

    uint32_t a_addr[4], b_addr[2];
    {
        const int r = wm + (lane & 15);
        const int c = (lane >> 4) * 16;
        #pragma unroll
        for (int mi = 0; mi < 4; mi++)
            a_addr[mi] = sb + (r + mi * 16) * 48 + c;
        const int n = wn + (lane & 7) + (lane >> 4) * 8;
        const int kc = ((lane >> 3) & 1) * 16;
        #pragma unroll
        for (int nc = 0; nc < 2; nc++)
            b_addr[nc] = sb + 2 * TILEB + (n + nc * 16) * 48 + kc;
    }

    float acc[4][4][4];
    #pragma unroll
    for (int mi = 0; mi < 4; mi++)
        #pragma unroll
        for (int ni = 0; ni < 4; ni++)
            #pragma unroll
            for (int e = 0; e < 4; e++) acc[mi][ni][e] = 0.f;

    const int NT = Cn / 16;    // 48
    auto load_stage = [&](int t) {
        const uint32_t off = (t % 3) * STAGEB;
        const int k0 = t * 16;
        #pragma unroll
        for (int m4 = 0; m4 < 4; m4++)
            cpasync16(dstb + off + m4 * TILEB, (const void*)(srcs[m4] + k0));
        asm volatile("cp.async.commit_group;");
    };

    load_stage(0);
    load_stage(1);
    for (int t = 0; t < NT; t++) {
        if (t < NT - 1) asm volatile("cp.async.wait_group 1;");
        else            asm volatile("cp.async.wait_group 0;");
        __syncthreads();
        if (t + 2 < NT) load_stage(t + 2);

        const uint32_t off = (t % 3) * STAGEB;
        uint32_t fah[4][4], fal[4][4], fbh[2][4], fbl[2][4];
        #pragma unroll
        for (int mi = 0; mi < 4; mi++) {
            ldsm4(fah[mi], a_addr[mi] + off);
            ldsm4(fal[mi], a_addr[mi] + off + TILEB);
        }
        #pragma unroll
        for (int nc = 0; nc < 2; nc++) {
            ldsm4(fbh[nc], b_addr[nc] + off);
            ldsm4(fbl[nc], b_addr[nc] + off + TILEB);
        }
        #pragma unroll
        for (int mi = 0; mi < 4; mi++)
            #pragma unroll
            for (int ni = 0; ni < 4; ni++) {
                const int nc = ni >> 1, sel = (ni & 1) * 2;
                mma16816(acc[mi][ni], fah[mi], &fbh[nc][sel]);
                mma16816(acc[mi][ni], fah[mi], &fbl[nc][sel]);
                mma16816(acc[mi][ni], fal[mi], &fbh[nc][sel]);
            }
    }

    // ---- epilogue: vectorized pair stores (n, n+1 adjacent in each e-pair)
    const int g = lane >> 2, t4 = lane & 3;
    #pragma unroll
    for (int mi = 0; mi < 4; mi++) {
        #pragma unroll
        for (int ni = 0; ni < 4; ni++) {
            const int n = j0 + wn + ni * 8 + t4 * 2;
            #pragma unroll
            for (int hp = 0; hp < 2; hp++) {     // e-pairs (0,1) and (2,3)
                const int m = i0 + wm + mi * 16 + g + hp * 8;
                const float r0 = acc[mi][ni][2 * hp];
                const float r1 = acc[mi][ni][2 * hp + 1];
                if (MODE == 0) {
                    const float v0 = r0 + bias[n], v1 = r1 + bias[n + 1];
                    __nv_bfloat162 hh, ll;
                    if (n < Cn) {
                        const long ix = (long)m * Cn + n;
                        split2(v0, v1, hh, ll);
                        *(__nv_bfloat162*)(g_qh + ix) = hh;
                        *(__nv_bfloat162*)(g_ql + ix) = ll;
                        split2(v0 * selw[n >> 6], v1 * selw[(n + 1) >> 6], hh, ll);
                        *(__nv_bfloat162*)(g_qsh + ix) = hh;
                        *(__nv_bfloat162*)(g_qsl + ix) = ll;
                    } else if (n < 2 * Cn) {
                        const long ix = (long)m * Cn + n - Cn;
                        split2(v0, v1, hh, ll);
                        *(__nv_bfloat162*)(g_kh + ix) = hh;
                        *(__nv_bfloat162*)(g_kl + ix) = ll;
                    } else {
                        const long ix = (long)m * Cn + n - 2 * Cn;
                        split2(v0, v1, hh, ll);
                        *(__nv_bfloat162*)(g_vh + ix) = hh;
                        *(__nv_bfloat162*)(g_vl + ix) = ll;
                    }
                } else if (MODE == 1) {
                    float v0 = r0 * SCALE, v1 = r1 * SCALE;
                    v0 = (n     >= 1 && n     < m) ? fmaxf(v0, 0.f) : 0.f;
                    v1 = (n + 1 >= 1 && n + 1 < m) ? fmaxf(v1, 0.f) : 0.f;
                    *(float2*)(g_ff + (long)bz * Tn * Tn + (long)m * Tn + n)
                        = make_float2(v0, v1);
                } else {
                    *(float2*)(Cout + (long)m * Cn + n)
                        = make_float2(r0 + bias[n], r1 + bias[n + 1]);
                }
            }
        }
    }
}

// ============================================================================
// Parallel exclusive cumsum of S over rows i (NSEG=32 segments of 64 rows).
// Segments fully above the diagonal (all rows i <= j) are skipped: their
// partial is 0 and their FF cells are never consumed (masked in attention).
// ============================================================================
__global__ void cumsum_p1()
{
    const int g = blockIdx.x * 256 + threadIdx.x;
    const int j = g & (Tn - 1);
    const int seg = (g >> 11) & (NSEG - 1);
    const int b = g >> 16;
    const int ibeg = seg * (Tn / NSEG);
    if (ibeg + (Tn / NSEG) - 1 <= j) { g_part[g] = 0.f; return; }
    const float* col = g_ff + (long)b * Tn * Tn + j;
    float s = 0.f;
    #pragma unroll 8
    for (int k = 0; k < Tn / NSEG; k++) {
        const int i = ibeg + k;
        const float v = col[(long)i * Tn];
        if (i > j) s += v;
    }
    g_part[g] = s;
}

__global__ void cumsum_p2()
{
    const int g = blockIdx.x * 256 + threadIdx.x;
    const int j = g & (Tn - 1);
    const int seg = (g >> 11) & (NSEG - 1);
    const int b = g >> 16;
    const int ibeg = seg * (Tn / NSEG);
    if (ibeg + (Tn / NSEG) - 1 <= j) return;   // unused region
    const float* pp = g_part + (b << 16) + j;
    float acc = 0.f;
    for (int s2 = 0; s2 < seg; s2++) acc += pp[s2 << 11];
    float* col = g_ff + (long)b * Tn * Tn + j;
    #pragma unroll 8
    for (int k = 0; k < Tn / NSEG; k++) {
        const int i = ibeg + k;
        const float v = col[(long)i * Tn];
        col[(long)i * Tn] = acc;          // exclusive prefix (FF_shifted)
        if (i > j) acc += v;
    }
}

// ============================================================================
// Tensor-core flash attention with forgetting term.
// Block = (q tile of 128 rows) x (b,h); bx REVERSED so heavy tiles launch
// first (LPT balance). 8 warps, 16 rows each. KV tiles of 64.
// ============================================================================
#define BR 128
#define BC 64
#define QTB 18432            // 128 * 144 B (one Q tile, bf16, pitch 72 halves)
#define KVB 9216             // 64 * 144 B
#define STG (4 * KVB)        // 36864
#define ATT_SMEM (2 * QTB + 2 * STG)   // 110592

__global__ void __launch_bounds__(256) attn_mma()
{
    const int bx = gridDim.x - 1 - blockIdx.x;   // heavy blocks first
    const int bh = blockIdx.y;
    const int b = bh / Hn, h = bh % Hn;
    const int tid = threadIdx.x, lane = tid & 31, wid = tid >> 5;
    const int i0 = bx * BR;

    extern __shared__ __align__(16) char sm[];
    const uint32_t sb = smem_u32(sm);

    const __nv_bfloat16* gq_h = g_qh + (long)(b * Tn + i0) * Cn + h * HDn;
    const __nv_bfloat16* gq_l = g_ql + (long)(b * Tn + i0) * Cn + h * HDn;
    const __nv_bfloat16* gk_h = g_kh + (long)b * Tn * Cn + h * HDn;
    const __nv_bfloat16* gk_l = g_kl + (long)b * Tn * Cn + h * HDn;
    const __nv_bfloat16* gv_h = g_vh + (long)b * Tn * Cn + h * HDn;
    const __nv_bfloat16* gv_l = g_vl + (long)b * Tn * Cn + h * HDn;
    const float* gf = g_ff + (long)b * Tn * Tn + (long)i0 * Tn;

    auto ld_tile = [&](int t) {
        const uint32_t st = sb + 2 * QTB + (t & 1) * STG;
        const int j0 = t * BC;
        const int r = tid >> 2;
        const int cb = (tid & 3) * 2;
        #pragma unroll
        for (int u = 0; u < 2; u++) {
            const int c = cb + u;
            const long so = (long)(j0 + r) * Cn + c * 8;
            const uint32_t d = st + r * 144 + c * 16;
            cpasync16(d,           gk_h + so);
            cpasync16(d + KVB,     gk_l + so);
            cpasync16(d + 2 * KVB, gv_h + so);
            cpasync16(d + 3 * KVB, gv_l + so);
        }
        asm volatile("cp.async.commit_group;");
    };

    // Q tiles + tile 0 into group 0
    {
        const int r = tid >> 1, c0 = (tid & 1) * 4;
        #pragma unroll
        for (int u = 0; u < 4; u++) {
            const long so = (long)r * Cn + (c0 + u) * 8;
            cpasync16(sb + r * 144 + (c0 + u) * 16,       gq_h + so);
            cpasync16(sb + QTB + r * 144 + (c0 + u) * 16, gq_l + so);
        }
    }
    ld_tile(0);

    uint32_t qa_h[4][4], qa_l[4][4];
    float o[8][4];
    #pragma unroll
    for (int f = 0; f < 8; f++)
        #pragma unroll
        for (int e = 0; e < 4; e++) o[f][e] = 0.f;
    float mrow[2] = {-INFINITY, -INFINITY};
    float lrow[2] = {0.f, 0.f};

    const int g = lane >> 2, t4 = lane & 3;
    const int nt = 2 * bx + 2;

    for (int t = 0; t < nt; t++) {
        if (t + 1 < nt) {
            ld_tile(t + 1);
            asm volatile("cp.async.wait_group 1;");
        } else {
            asm volatile("cp.async.wait_group 0;");
        }
        __syncthreads();

        const uint32_t st = sb + 2 * QTB + (t & 1) * STG;
        const int j0 = t * BC;

        if (t == 0) {   // Q fragments (once)
            #pragma unroll
            for (int dc = 0; dc < 4; dc++) {
                const uint32_t qa = sb + (wid * 16 + (lane & 15)) * 144
                                  + dc * 32 + (lane >> 4) * 16;
                ldsm4(qa_h[dc], qa);
                ldsm4(qa_l[dc], qa + QTB);
            }
        }

        const bool skip = (j0 > i0 + wid * 16 + 15);   // warp fully masked
        if (!skip) {
            // ---- prefetch FF pairs into regs (overlaps with MMA below)
            float2 fv[2][8];
            #pragma unroll
            for (int half = 0; half < 2; half++) {
                const float* fr = gf + (long)(wid * 16 + g + half * 8) * Tn
                                + j0 + 2 * t4;
                #pragma unroll
                for (int f = 0; f < 8; f++)
                    fv[half][f] = *(const float2*)(fr + f * 8);
            }

            // ---- S = Q K^T (3 products)
            float sfr[8][4];
            #pragma unroll
            for (int f = 0; f < 8; f++)
                #pragma unroll
                for (int e = 0; e < 4; e++) sfr[f][e] = 0.f;
            #pragma unroll
            for (int jg = 0; jg < 4; jg++) {
                uint32_t kbh[4][4], kbl[4][4];
                const uint32_t ka = st + (jg * 16 + (lane & 7) + (lane >> 4) * 8) * 144
                                  + ((lane >> 3) & 1) * 16;
                #pragma unroll
                for (int dc = 0; dc < 4; dc++) {
                    ldsm4(kbh[dc], ka + dc * 32);
                    ldsm4(kbl[dc], ka + dc * 32 + KVB);
                }
                #pragma unroll
                for (int dc = 0; dc < 4; dc++) {
                    mma16816(sfr[2 * jg],     qa_h[dc], &kbh[dc][0]);
                    mma16816(sfr[2 * jg],     qa_h[dc], &kbl[dc][0]);
                    mma16816(sfr[2 * jg],     qa_l[dc], &kbh[dc][0]);
                    mma16816(sfr[2 * jg + 1], qa_h[dc], &kbh[dc][2]);
                    mma16816(sfr[2 * jg + 1], qa_h[dc], &kbl[dc][2]);
                    mma16816(sfr[2 * jg + 1], qa_l[dc], &kbh[dc][2]);
                }
            }

            // ---- softmax with FF (per row-half)
            const bool domask = (t >= 2 * bx);
            #pragma unroll
            for (int half = 0; half < 2; half++) {
                const int irow = i0 + wid * 16 + g + half * 8;
                float vmax = -INFINITY;
                #pragma unroll
                for (int f = 0; f < 8; f++) {
                    float s0 = sfr[f][2 * half]     * SCALE - fv[half][f].x;
                    float s1 = sfr[f][2 * half + 1] * SCALE - fv[half][f].y;
                    if (domask) {
                        const int j = j0 + f * 8 + 2 * t4;
                        if (j     > irow) s0 = -INFINITY;
                        if (j + 1 > irow) s1 = -INFINITY;
                    }
                    sfr[f][2 * half] = s0; sfr[f][2 * half + 1] = s1;
                    vmax = fmaxf(vmax, fmaxf(s0, s1));
                }
                vmax = fmaxf(vmax, __shfl_xor_sync(0xffffffffu, vmax, 1));
                vmax = fmaxf(vmax, __shfl_xor_sync(0xffffffffu, vmax, 2));
                const float mnew = fmaxf(mrow[half], vmax);
                const float scl = __expf(mrow[half] - mnew);
                mrow[half] = mnew;
                float ls = 0.f;
                #pragma unroll
                for (int f = 0; f < 8; f++) {
                    const float p0 = __expf(sfr[f][2 * half]     - mnew);
                    const float p1 = __expf(sfr[f][2 * half + 1] - mnew);
                    sfr[f][2 * half] = p0; sfr[f][2 * half + 1] = p1;
                    ls += p0 + p1;
                }
                lrow[half] = lrow[half] * scl + ls;
                #pragma unroll
                for (int f = 0; f < 8; f++) {
                    o[f][2 * half]     *= scl;
                    o[f][2 * half + 1] *= scl;
                }
            }

            // ---- P -> bf16 hi/lo A-fragments
            uint32_t pa_h[4][4], pa_l[4][4];
            #pragma unroll
            for (int jc = 0; jc < 4; jc++) {
                #pragma unroll
                for (int rr = 0; rr < 4; rr++) {
                    const int f = 2 * jc + (rr >> 1);
                    const int e = (rr & 1) * 2;
                    __nv_bfloat162 ph, pl;
                    split2(sfr[f][e], sfr[f][e + 1], ph, pl);
                    pa_h[jc][rr] = *(uint32_t*)&ph;
                    pa_l[jc][rr] = *(uint32_t*)&pl;
                }
            }

            // ---- O += P V (3 products), V via trans ldmatrix
            #pragma unroll
            for (int dg = 0; dg < 4; dg++) {
                uint32_t vbh[4][4], vbl[4][4];
                #pragma unroll
                for (int jc = 0; jc < 4; jc++) {
                    const uint32_t va = st + 2 * KVB
                        + (jc * 16 + (lane & 7) + ((lane >> 3) & 1) * 8) * 144
                        + dg * 32 + (lane >> 4) * 16;
                    ldsm4t(vbh[jc], va);
                    ldsm4t(vbl[jc], va + KVB);
                }
                #pragma unroll
                for (int jc = 0; jc < 4; jc++) {
                    mma16816(o[2 * dg],     pa_h[jc], &vbh[jc][0]);
                    mma16816(o[2 * dg],     pa_h[jc], &vbl[jc][0]);
                    mma16816(o[2 * dg],     pa_l[jc], &vbh[jc][0]);
                    mma16816(o[2 * dg + 1], pa_h[jc], &vbh[jc][2]);
                    mma16816(o[2 * dg + 1], pa_h[jc], &vbl[jc][2]);
                    mma16816(o[2 * dg + 1], pa_l[jc], &vbh[jc][2]);
                }
            }
        }
        __syncthreads();
    }

    // ---- normalize and store y as bf16 hi/lo
    #pragma unroll
    for (int half = 0; half < 2; half++) {
        lrow[half] += __shfl_xor_sync(0xffffffffu, lrow[half], 1);
        lrow[half] += __shfl_xor_sync(0xffffffffu, lrow[half], 2);
    }
    const float inv[2] = {1.f / lrow[0], 1.f / lrow[1]};
    #pragma unroll
    for (int half = 0; half < 2; half++) {
        const long row = (long)(b * Tn + i0 + wid * 16 + g + half * 8);
        #pragma unroll
        for (int f = 0; f < 8; f++) {
            const float a0 = o[f][2 * half]     * inv[half];
            const float a1 = o[f][2 * half + 1] * inv[half];
            __nv_bfloat162 yh, yl;
            split2(a0, a1, yh, yl);
            const long off = row * Cn + h * HDn + f * 8 + 2 * t4;
            *(__nv_bfloat162*)(g_yh + off) = yh;
            *(__nv_bfloat162*)(g_yl + off) = yl;
        }
    }
}

// ============================================================================
extern "C" void kernel_launch(void* const* d_in, const int* in_sizes, int n_in,
                              void* d_out, int out_size)
{
    const float* x      = (const float*)d_in[0];
    const float* w_attn = (const float*)d_in[1];
    const float* b_attn = (const float*)d_in[2];
    const float* w_proj = (const float*)d_in[3];
    const float* b_proj = (const float*)d_in[4];
    const float* sel_w  = (const float*)d_in[5];
    float* out = (float*)d_out;

    __nv_bfloat16 *xh, *xl, *wah, *wal, *wph, *wpl, *qsh, *qsl, *kh, *kl, *yh, *yl;
    cudaGetSymbolAddress((void**)&xh,  g_xh);  cudaGetSymbolAddress((void**)&xl,  g_xl);
    cudaGetSymbolAddress((void**)&wah, g_wah); cudaGetSymbolAddress((void**)&wal, g_wal);
    cudaGetSymbolAddress((void**)&wph, g_wph); cudaGetSymbolAddress((void**)&wpl, g_wpl);
    cudaGetSymbolAddress((void**)&qsh, g_qsh); cudaGetSymbolAddress((void**)&qsl, g_qsl);
    cudaGetSymbolAddress((void**)&kh,  g_kh);  cudaGetSymbolAddress((void**)&kl,  g_kl);
    cudaGetSymbolAddress((void**)&yh,  g_yh);  cudaGetSymbolAddress((void**)&yl,  g_yl);

    static bool attr_done = false;
    if (!attr_done) {
        cudaFuncSetAttribute(attn_mma,
            cudaFuncAttributeMaxDynamicSharedMemorySize, ATT_SMEM);
        cudaFuncSetAttribute(gemm_mma<0>,
            cudaFuncAttributeMaxDynamicSharedMemorySize, GEMM_SMEM);
        cudaFuncSetAttribute(gemm_mma<1>,
            cudaFuncAttributeMaxDynamicSharedMemorySize, GEMM_SMEM);
        cudaFuncSetAttribute(gemm_mma<2>,
            cudaFuncAttributeMaxDynamicSharedMemorySize, GEMM_SMEM);
        attr_done = true;
    }

    // 0) fused bf16 hi/lo splits of inputs
    split_all<<<(N_X + N_WA + N_WP) / 256, 256>>>(x, w_attn, w_proj);

    // 1) qkv GEMM (epilogue splits q/qs/k/v into bf16 hi/lo buffers)
    gemm_mma<0><<<dim3(QKVn / 128, (Bn * Tn) / 128, 1), 256, GEMM_SMEM>>>(
        xh, xl, wah, wal, Cn, Cn, 0, 0, b_attn, sel_w, nullptr);

    // 2) S = relu(scale * qs @ k^T), masked
    gemm_mma<1><<<dim3(Tn / 128, Tn / 128, Bn), 256, GEMM_SMEM>>>(
        qsh, qsl, kh, kl, Cn, Cn, (long)Tn * Cn, (long)Tn * Cn,
        nullptr, nullptr, nullptr);

    // 3) FF_shifted = exclusive cumsum of S over rows (triangle-skipped)
    cumsum_p1<<<(Bn * NSEG * Tn) / 256, 256>>>();
    cumsum_p2<<<(Bn * NSEG * Tn) / 256, 256>>>();

    // 4) tensor-core flash attention with forgetting term
    attn_mma<<<dim3(Tn / BR, Bn * Hn), 256, ATT_SMEM>>>();

    // 5) out = y @ w_proj^T + b_proj
    gemm_mma<2><<<dim3(Cn / 128, (Bn * Tn) / 128, 1), 256, GEMM_SMEM>>>(
        yh, yl, wph, wpl, Cn, Cn, 0, 0, b_proj, nullptr, out);
}

// round 16
// speedup vs baseline: 1.0197x; 1.0197x over previous
#include <cuda_runtime.h>
#include <cuda_bf16.h>
#include <math.h>
#include <stdint.h>

#define Bn   2
#define Tn   2048
#define Cn   768
#define Hn   12
#define HDn  64
#define QKVn 2304
#define SCALE 0.125f   // 1/sqrt(64)
#define NSEG 32        // cumsum segments (64 rows each)

// -------- device scratch (no allocations allowed) --------
__device__ float g_ff  [Bn * Tn * Tn];       // S, then exclusive cumsum
__device__ float g_part[Bn * NSEG * Tn];     // cumsum segment partials
__device__ __nv_bfloat16 g_xh [Bn*Tn*Cn], g_xl [Bn*Tn*Cn];
__device__ __nv_bfloat16 g_wah[QKVn*Cn],  g_wal[QKVn*Cn];
__device__ __nv_bfloat16 g_wph[Cn*Cn],    g_wpl[Cn*Cn];
__device__ __nv_bfloat16 g_qh [Bn*Tn*Cn], g_ql [Bn*Tn*Cn];  // raw q (attn)
__device__ __nv_bfloat16 g_qsh[Bn*Tn*Cn], g_qsl[Bn*Tn*Cn];  // sel_w-scaled q
__device__ __nv_bfloat16 g_kh [Bn*Tn*Cn], g_kl [Bn*Tn*Cn];
__device__ __nv_bfloat16 g_vh [Bn*Tn*Cn], g_vl [Bn*Tn*Cn];
__device__ __nv_bfloat16 g_yh [Bn*Tn*Cn], g_yl [Bn*Tn*Cn];

// ======================= PTX helpers (compute_103-safe) ====================
__device__ __forceinline__ uint32_t smem_u32(const void* p) {
    uint32_t a;
    asm("{ .reg .u64 t; cvta.to.shared.u64 t, %1; cvt.u32.u64 %0, t; }"
        : "=r"(a) : "l"(p));
    return a;
}
__device__ __forceinline__ void ldsm4(uint32_t* r, uint32_t addr) {
    asm volatile("ldmatrix.sync.aligned.m8n8.x4.shared.b16 {%0,%1,%2,%3}, [%4];"
                 : "=r"(r[0]), "=r"(r[1]), "=r"(r[2]), "=r"(r[3]) : "r"(addr));
}
__device__ __forceinline__ void ldsm4t(uint32_t* r, uint32_t addr) {
    asm volatile("ldmatrix.sync.aligned.m8n8.x4.trans.shared.b16 {%0,%1,%2,%3}, [%4];"
                 : "=r"(r[0]), "=r"(r[1]), "=r"(r[2]), "=r"(r[3]) : "r"(addr));
}
__device__ __forceinline__ void mma16816(float* c, const uint32_t* a, const uint32_t* b) {
    asm volatile(
        "mma.sync.aligned.m16n8k16.row.col.f32.bf16.bf16.f32 "
        "{%0,%1,%2,%3}, {%4,%5,%6,%7}, {%8,%9}, {%0,%1,%2,%3};"
        : "+f"(c[0]), "+f"(c[1]), "+f"(c[2]), "+f"(c[3])
        : "r"(a[0]), "r"(a[1]), "r"(a[2]), "r"(a[3]), "r"(b[0]), "r"(b[1]));
}
__device__ __forceinline__ void cpasync16(uint32_t dst, const void* src) {
    asm volatile("cp.async.cg.shared.global [%0], [%1], 16;" :: "r"(dst), "l"(src));
}
// pack (v0, v1) into hi bf16x2 + lo (residual) bf16x2
__device__ __forceinline__ void split2(float v0, float v1,
                                       __nv_bfloat162& hh, __nv_bfloat162& ll) {
    hh.x = __float2bfloat16(v0);
    hh.y = __float2bfloat16(v1);
    ll.x = __float2bfloat16(v0 - __bfloat162float(hh.x));
    ll.y = __float2bfloat16(v1 - __bfloat162float(hh.y));
}

// ============================================================================
// Fused bf16 split of all three fp32 inputs (x, w_attn, w_proj) -> hi/lo
// ============================================================================
#define N_X  (Bn * Tn * Cn)
#define N_WA (QKVn * Cn)
#define N_WP (Cn * Cn)

__global__ void split_all(const float* __restrict__ x,
                          const float* __restrict__ wa,
                          const float* __restrict__ wp)
{
    const int i = blockIdx.x * 256 + threadIdx.x;
    float v; __nv_bfloat16* hd; __nv_bfloat16* ld; int ix;
    if (i < N_X) {
        v = x[i]; hd = g_xh; ld = g_xl; ix = i;
    } else if (i < N_X + N_WA) {
        ix = i - N_X; v = wa[ix]; hd = g_wah; ld = g_wal;
    } else {
        ix = i - N_X - N_WA; v = wp[ix]; hd = g_wph; ld = g_wpl;
    }
    const __nv_bfloat16 hh = __float2bfloat16(v);
    hd[ix] = hh;
    ld[ix] = __float2bfloat16(v - __bfloat162float(hh));
}

// ============================================================================
// bf16x3 tensor-core GEMM (HMMA): C[m,n]=sum_k A[m,k]*B[n,k]
// AhBh+AhBl+AlBh, fp32 accum. 128x128 block, BK=16, 8 warps, cp.async x2
// (static 48KB smem — the R11-measured-good config).
// __launch_bounds__(256,2): regs<=128 -> 2 CTAs/SM.
// MODE 0 qkv (bias + split-scatter q/qs/k/v) / 1 selection-S / 2 proj.
// ============================================================================
#define TILEB 6144          // 128 rows * 48 bytes
#define STAGEB (4 * TILEB)  // Ah, Al, Bh, Bl

template <int MODE>
__global__ void __launch_bounds__(256, 2)
gemm_mma(const __nv_bfloat16* __restrict__ Ah, const __nv_bfloat16* __restrict__ Al,
         const __nv_bfloat16* __restrict__ Bh, const __nv_bfloat16* __restrict__ Bl,
         int lda, int ldb, long sA, long sB,
         const float* __restrict__ bias, const float* __restrict__ selw,
         float* __restrict__ Cout)
{
    const int i0 = blockIdx.y * 128, j0 = blockIdx.x * 128, bz = blockIdx.z;
    if (MODE == 1 && j0 > i0) return;        // strictly-upper tiles: zero, never read
    Ah += (long)bz * sA; Al += (long)bz * sA;
    Bh += (long)bz * sB; Bl += (long)bz * sB;

    __shared__ __align__(128) char sm[2 * STAGEB];   // 48 KB
    const uint32_t sb = smem_u32(sm);

    const int tid = threadIdx.x;
    const int lane = tid & 31, wid = tid >> 5;
    const int wm = (wid & 1) * 64, wn = (wid >> 1) * 32;

    const int lrow = tid >> 1, lhalf = tid & 1;
    const __nv_bfloat16* srcs[4] = {
        Ah + (long)(i0 + lrow) * lda + lhalf * 8,
        Al + (long)(i0 + lrow) * lda + lhalf * 8,
        Bh + (long)(j0 + lrow) * ldb + lhalf * 8,
        Bl + (long)(j0 + lrow) * ldb + lhalf * 8 };
    const uint32_t dstb = sb + lrow * 48 + lhalf * 16;

    uint32_t a_addr[4], b_addr[2];
    {
        const int r = wm + (lane & 15);
        const int c = (lane >> 4) * 16;
        #pragma unroll
        for (int mi = 0; mi < 4; mi++)
            a_addr[mi] = sb + (r + mi * 16) * 48 + c;
        const int n = wn + (lane & 7) + (lane >> 4) * 8;
        const int kc = ((lane >> 3) & 1) * 16;
        #pragma unroll
        for (int nc = 0; nc < 2; nc++)
            b_addr[nc] = sb + 2 * TILEB + (n + nc * 16) * 48 + kc;
    }

    float acc[4][4][4];
    #pragma unroll
    for (int mi = 0; mi < 4; mi++)
        #pragma unroll
        for (int ni = 0; ni < 4; ni++)
            #pragma unroll
            for (int e = 0; e < 4; e++) acc[mi][ni][e] = 0.f;

    const int NT = Cn / 16;    // 48
    auto load_stage = [&](int t) {
        const uint32_t off = (t & 1) * STAGEB;
        const int k0 = t * 16;
        #pragma unroll
        for (int m4 = 0; m4 < 4; m4++)
            cpasync16(dstb + off + m4 * TILEB, (const void*)(srcs[m4] + k0));
        asm volatile("cp.async.commit_group;");
    };

    load_stage(0);
    for (int t = 0; t < NT; t++) {
        if (t + 1 < NT) {
            load_stage(t + 1);
            asm volatile("cp.async.wait_group 1;");
        } else {
            asm volatile("cp.async.wait_group 0;");
        }
        __syncthreads();

        const uint32_t off = (t & 1) * STAGEB;
        uint32_t fah[4][4], fal[4][4], fbh[2][4], fbl[2][4];
        #pragma unroll
        for (int mi = 0; mi < 4; mi++) {
            ldsm4(fah[mi], a_addr[mi] + off);
            ldsm4(fal[mi], a_addr[mi] + off + TILEB);
        }
        #pragma unroll
        for (int nc = 0; nc < 2; nc++) {
            ldsm4(fbh[nc], b_addr[nc] + off);
            ldsm4(fbl[nc], b_addr[nc] + off + TILEB);
        }
        #pragma unroll
        for (int mi = 0; mi < 4; mi++)
            #pragma unroll
            for (int ni = 0; ni < 4; ni++) {
                const int nc = ni >> 1, sel = (ni & 1) * 2;
                mma16816(acc[mi][ni], fah[mi], &fbh[nc][sel]);
                mma16816(acc[mi][ni], fah[mi], &fbl[nc][sel]);
                mma16816(acc[mi][ni], fal[mi], &fbh[nc][sel]);
            }
        __syncthreads();
    }

    // ---- epilogue: vectorized pair stores (n, n+1 adjacent in each e-pair)
    const int g = lane >> 2, t4 = lane & 3;
    #pragma unroll
    for (int mi = 0; mi < 4; mi++) {
        #pragma unroll
        for (int ni = 0; ni < 4; ni++) {
            const int n = j0 + wn + ni * 8 + t4 * 2;
            #pragma unroll
            for (int hp = 0; hp < 2; hp++) {     // e-pairs (0,1) and (2,3)
                const int m = i0 + wm + mi * 16 + g + hp * 8;
                const float r0 = acc[mi][ni][2 * hp];
                const float r1 = acc[mi][ni][2 * hp + 1];
                if (MODE == 0) {
                    const float v0 = r0 + bias[n], v1 = r1 + bias[n + 1];
                    __nv_bfloat162 hh, ll;
                    if (n < Cn) {
                        const long ix = (long)m * Cn + n;
                        split2(v0, v1, hh, ll);
                        *(__nv_bfloat162*)(g_qh + ix) = hh;
                        *(__nv_bfloat162*)(g_ql + ix) = ll;
                        split2(v0 * selw[n >> 6], v1 * selw[(n + 1) >> 6], hh, ll);
                        *(__nv_bfloat162*)(g_qsh + ix) = hh;
                        *(__nv_bfloat162*)(g_qsl + ix) = ll;
                    } else if (n < 2 * Cn) {
                        const long ix = (long)m * Cn + n - Cn;
                        split2(v0, v1, hh, ll);
                        *(__nv_bfloat162*)(g_kh + ix) = hh;
                        *(__nv_bfloat162*)(g_kl + ix) = ll;
                    } else {
                        const long ix = (long)m * Cn + n - 2 * Cn;
                        split2(v0, v1, hh, ll);
                        *(__nv_bfloat162*)(g_vh + ix) = hh;
                        *(__nv_bfloat162*)(g_vl + ix) = ll;
                    }
                } else if (MODE == 1) {
                    float v0 = r0 * SCALE, v1 = r1 * SCALE;
                    v0 = (n     >= 1 && n     < m) ? fmaxf(v0, 0.f) : 0.f;
                    v1 = (n + 1 >= 1 && n + 1 < m) ? fmaxf(v1, 0.f) : 0.f;
                    *(float2*)(g_ff + (long)bz * Tn * Tn + (long)m * Tn + n)
                        = make_float2(v0, v1);
                } else {
                    *(float2*)(Cout + (long)m * Cn + n)
                        = make_float2(r0 + bias[n], r1 + bias[n + 1]);
                }
            }
        }
    }
}

// ============================================================================
// Parallel exclusive cumsum of S over rows i (NSEG=32 segments of 64 rows).
// Segments fully above the diagonal are skipped (unused, masked downstream).
// ============================================================================
__global__ void cumsum_p1()
{
    const int g = blockIdx.x * 256 + threadIdx.x;
    const int j = g & (Tn - 1);
    const int seg = (g >> 11) & (NSEG - 1);
    const int b = g >> 16;
    const int ibeg = seg * (Tn / NSEG);
    if (ibeg + (Tn / NSEG) - 1 <= j) { g_part[g] = 0.f; return; }
    const float* col = g_ff + (long)b * Tn * Tn + j;
    float s = 0.f;
    #pragma unroll 8
    for (int k = 0; k < Tn / NSEG; k++) {
        const int i = ibeg + k;
        const float v = col[(long)i * Tn];
        if (i > j) s += v;
    }
    g_part[g] = s;
}

__global__ void cumsum_p2()
{
    const int g = blockIdx.x * 256 + threadIdx.x;
    const int j = g & (Tn - 1);
    const int seg = (g >> 11) & (NSEG - 1);
    const int b = g >> 16;
    const int ibeg = seg * (Tn / NSEG);
    if (ibeg + (Tn / NSEG) - 1 <= j) return;   // unused region
    const float* pp = g_part + (b << 16) + j;
    float acc = 0.f;
    for (int s2 = 0; s2 < seg; s2++) acc += pp[s2 << 11];
    float* col = g_ff + (long)b * Tn * Tn + j;
    #pragma unroll 8
    for (int k = 0; k < Tn / NSEG; k++) {
        const int i = ibeg + k;
        const float v = col[(long)i * Tn];
        col[(long)i * Tn] = acc;          // exclusive prefix (FF_shifted)
        if (i > j) acc += v;
    }
}

// ============================================================================
// Tensor-core flash attention with forgetting term.
// BR=64 rows per block, 4 warps (16 rows each), 128 threads, 2 CTAs/SM
// (smem 92KB/CTA, launch_bounds(128,2)) -> two independent CTAs overlap
// each other's softmax/MMA dependency bubbles. KV tiles of 64, cp.async x2.
// bx REVERSED so heavy tiles launch first (LPT balance).
// ============================================================================
#define BR 64
#define BC 64
#define QTB 9216             // 64 * 144 B (one Q tile, bf16, pitch 72 halves)
#define KVB 9216             // 64 * 144 B
#define STG (4 * KVB)        // 36864
#define ATT_SMEM (2 * QTB + 2 * STG)   // 92160

__global__ void __launch_bounds__(128, 2) attn_mma()
{
    const int bx = gridDim.x - 1 - blockIdx.x;   // heavy blocks first
    const int bh = blockIdx.y;
    const int b = bh / Hn, h = bh % Hn;
    const int tid = threadIdx.x, lane = tid & 31, wid = tid >> 5;   // wid 0..3
    const int i0 = bx * BR;

    extern __shared__ __align__(16) char sm[];
    const uint32_t sb = smem_u32(sm);

    const __nv_bfloat16* gq_h = g_qh + (long)(b * Tn + i0) * Cn + h * HDn;
    const __nv_bfloat16* gq_l = g_ql + (long)(b * Tn + i0) * Cn + h * HDn;
    const __nv_bfloat16* gk_h = g_kh + (long)b * Tn * Cn + h * HDn;
    const __nv_bfloat16* gk_l = g_kl + (long)b * Tn * Cn + h * HDn;
    const __nv_bfloat16* gv_h = g_vh + (long)b * Tn * Cn + h * HDn;
    const __nv_bfloat16* gv_l = g_vl + (long)b * Tn * Cn + h * HDn;
    const float* gf = g_ff + (long)b * Tn * Tn + (long)i0 * Tn;

    auto ld_tile = [&](int t) {
        const uint32_t st = sb + 2 * QTB + (t & 1) * STG;
        const int j0 = t * BC;
        const int r = tid >> 1;              // 0..63
        const int cb = (tid & 1) * 4;        // 4 of 8 16B-chunks per row
        #pragma unroll
        for (int u = 0; u < 4; u++) {
            const int c = cb + u;
            const long so = (long)(j0 + r) * Cn + c * 8;
            const uint32_t d = st + r * 144 + c * 16;
            cpasync16(d,           gk_h + so);
            cpasync16(d + KVB,     gk_l + so);
            cpasync16(d + 2 * KVB, gv_h + so);
            cpasync16(d + 3 * KVB, gv_l + so);
        }
        asm volatile("cp.async.commit_group;");
    };

    // Q tiles + tile 0 into group 0 (64 rows x 8 chunks x 2 halves)
    {
        const int r = tid >> 1, c0 = (tid & 1) * 4;
        #pragma unroll
        for (int u = 0; u < 4; u++) {
            const long so = (long)r * Cn + (c0 + u) * 8;
            cpasync16(sb + r * 144 + (c0 + u) * 16,       gq_h + so);
            cpasync16(sb + QTB + r * 144 + (c0 + u) * 16, gq_l + so);
        }
    }
    ld_tile(0);

    uint32_t qa_h[4][4], qa_l[4][4];
    float o[8][4];
    #pragma unroll
    for (int f = 0; f < 8; f++)
        #pragma unroll
        for (int e = 0; e < 4; e++) o[f][e] = 0.f;
    float mrow[2] = {-INFINITY, -INFINITY};
    float lrow[2] = {0.f, 0.f};

    const int g = lane >> 2, t4 = lane & 3;
    const int nt = bx + 1;

    for (int t = 0; t < nt; t++) {
        if (t + 1 < nt) {
            ld_tile(t + 1);
            asm volatile("cp.async.wait_group 1;");
        } else {
            asm volatile("cp.async.wait_group 0;");
        }
        __syncthreads();

        const uint32_t st = sb + 2 * QTB + (t & 1) * STG;
        const int j0 = t * BC;

        if (t == 0) {   // Q fragments (once)
            #pragma unroll
            for (int dc = 0; dc < 4; dc++) {
                const uint32_t qa = sb + (wid * 16 + (lane & 15)) * 144
                                  + dc * 32 + (lane >> 4) * 16;
                ldsm4(qa_h[dc], qa);
                ldsm4(qa_l[dc], qa + QTB);
            }
        }

        {
            // ---- prefetch FF pairs into regs (overlaps with MMA below)
            float2 fv[2][8];
            #pragma unroll
            for (int half = 0; half < 2; half++) {
                const float* fr = gf + (long)(wid * 16 + g + half * 8) * Tn
                                + j0 + 2 * t4;
                #pragma unroll
                for (int f = 0; f < 8; f++)
                    fv[half][f] = *(const float2*)(fr + f * 8);
            }

            // ---- S = Q K^T (3 products)
            float sfr[8][4];
            #pragma unroll
            for (int f = 0; f < 8; f++)
                #pragma unroll
                for (int e = 0; e < 4; e++) sfr[f][e] = 0.f;
            #pragma unroll
            for (int jg = 0; jg < 4; jg++) {
                uint32_t kbh[4][4], kbl[4][4];
                const uint32_t ka = st + (jg * 16 + (lane & 7) + (lane >> 4) * 8) * 144
                                  + ((lane >> 3) & 1) * 16;
                #pragma unroll
                for (int dc = 0; dc < 4; dc++) {
                    ldsm4(kbh[dc], ka + dc * 32);
                    ldsm4(kbl[dc], ka + dc * 32 + KVB);
                }
                #pragma unroll
                for (int dc = 0; dc < 4; dc++) {
                    mma16816(sfr[2 * jg],     qa_h[dc], &kbh[dc][0]);
                    mma16816(sfr[2 * jg],     qa_h[dc], &kbl[dc][0]);
                    mma16816(sfr[2 * jg],     qa_l[dc], &kbh[dc][0]);
                    mma16816(sfr[2 * jg + 1], qa_h[dc], &kbh[dc][2]);
                    mma16816(sfr[2 * jg + 1], qa_h[dc], &kbl[dc][2]);
                    mma16816(sfr[2 * jg + 1], qa_l[dc], &kbh[dc][2]);
                }
            }

            // ---- softmax with FF (per row-half)
            const bool domask = (t >= bx);
            #pragma unroll
            for (int half = 0; half < 2; half++) {
                const int irow = i0 + wid * 16 + g + half * 8;
                float vmax = -INFINITY;
                #pragma unroll
                for (int f = 0; f < 8; f++) {
                    float s0 = sfr[f][2 * half]     * SCALE - fv[half][f].x;
                    float s1 = sfr[f][2 * half + 1] * SCALE - fv[half][f].y;
                    if (domask) {
                        const int j = j0 + f * 8 + 2 * t4;
                        if (j     > irow) s0 = -INFINITY;
                        if (j + 1 > irow) s1 = -INFINITY;
                    }
                    sfr[f][2 * half] = s0; sfr[f][2 * half + 1] = s1;
                    vmax = fmaxf(vmax, fmaxf(s0, s1));
                }
                vmax = fmaxf(vmax, __shfl_xor_sync(0xffffffffu, vmax, 1));
                vmax = fmaxf(vmax, __shfl_xor_sync(0xffffffffu, vmax, 2));
                const float mnew = fmaxf(mrow[half], vmax);
                const float scl = __expf(mrow[half] - mnew);
                mrow[half] = mnew;
                float ls = 0.f;
                #pragma unroll
                for (int f = 0; f < 8; f++) {
                    const float p0 = __expf(sfr[f][2 * half]     - mnew);
                    const float p1 = __expf(sfr[f][2 * half + 1] - mnew);
                    sfr[f][2 * half] = p0; sfr[f][2 * half + 1] = p1;
                    ls += p0 + p1;
                }
                lrow[half] = lrow[half] * scl + ls;
                #pragma unroll
                for (int f = 0; f < 8; f++) {
                    o[f][2 * half]     *= scl;
                    o[f][2 * half + 1] *= scl;
                }
            }

            // ---- P -> bf16 hi/lo A-fragments
            uint32_t pa_h[4][4], pa_l[4][4];
            #pragma unroll
            for (int jc = 0; jc < 4; jc++) {
                #pragma unroll
                for (int rr = 0; rr < 4; rr++) {
                    const int f = 2 * jc + (rr >> 1);
                    const int e = (rr & 1) * 2;
                    __nv_bfloat162 ph, pl;
                    split2(sfr[f][e], sfr[f][e + 1], ph, pl);
                    pa_h[jc][rr] = *(uint32_t*)&ph;
                    pa_l[jc][rr] = *(uint32_t*)&pl;
                }
            }

            // ---- O += P V (3 products), V via trans ldmatrix
            #pragma unroll
            for (int dg = 0; dg < 4; dg++) {
                uint32_t vbh[4][4], vbl[4][4];
                #pragma unroll
                for (int jc = 0; jc < 4; jc++) {
                    const uint32_t va = st + 2 * KVB
                        + (jc * 16 + (lane & 7) + ((lane >> 3) & 1) * 8) * 144
                        + dg * 32 + (lane >> 4) * 16;
                    ldsm4t(vbh[jc], va);
                    ldsm4t(vbl[jc], va + KVB);
                }
                #pragma unroll
                for (int jc = 0; jc < 4; jc++) {
                    mma16816(o[2 * dg],     pa_h[jc], &vbh[jc][0]);
                    mma16816(o[2 * dg],     pa_h[jc], &vbl[jc][0]);
                    mma16816(o[2 * dg],     pa_l[jc], &vbh[jc][0]);
                    mma16816(o[2 * dg + 1], pa_h[jc], &vbh[jc][2]);
                    mma16816(o[2 * dg + 1], pa_h[jc], &vbl[jc][2]);
                    mma16816(o[2 * dg + 1], pa_l[jc], &vbh[jc][2]);
                }
            }
        }
        __syncthreads();
    }

    // ---- normalize and store y as bf16 hi/lo
    #pragma unroll
    for (int half = 0; half < 2; half++) {
        lrow[half] += __shfl_xor_sync(0xffffffffu, lrow[half], 1);
        lrow[half] += __shfl_xor_sync(0xffffffffu, lrow[half], 2);
    }
    const float inv[2] = {1.f / lrow[0], 1.f / lrow[1]};
    #pragma unroll
    for (int half = 0; half < 2; half++) {
        const long row = (long)(b * Tn + i0 + wid * 16 + g + half * 8);
        #pragma unroll
        for (int f = 0; f < 8; f++) {
            const float a0 = o[f][2 * half]     * inv[half];
            const float a1 = o[f][2 * half + 1] * inv[half];
            __nv_bfloat162 yh, yl;
            split2(a0, a1, yh, yl);
            const long off = row * Cn + h * HDn + f * 8 + 2 * t4;
            *(__nv_bfloat162*)(g_yh + off) = yh;
            *(__nv_bfloat162*)(g_yl + off) = yl;
        }
    }
}

// ============================================================================
extern "C" void kernel_launch(void* const* d_in, const int* in_sizes, int n_in,
                              void* d_out, int out_size)
{
    const float* x      = (const float*)d_in[0];
    const float* w_attn = (const float*)d_in[1];
    const float* b_attn = (const float*)d_in[2];
    const float* w_proj = (const float*)d_in[3];
    const float* b_proj = (const float*)d_in[4];
    const float* sel_w  = (const float*)d_in[5];
    float* out = (float*)d_out;

    __nv_bfloat16 *xh, *xl, *wah, *wal, *wph, *wpl, *qsh, *qsl, *kh, *kl, *yh, *yl;
    cudaGetSymbolAddress((void**)&xh,  g_xh);  cudaGetSymbolAddress((void**)&xl,  g_xl);
    cudaGetSymbolAddress((void**)&wah, g_wah); cudaGetSymbolAddress((void**)&wal, g_wal);
    cudaGetSymbolAddress((void**)&wph, g_wph); cudaGetSymbolAddress((void**)&wpl, g_wpl);
    cudaGetSymbolAddress((void**)&qsh, g_qsh); cudaGetSymbolAddress((void**)&qsl, g_qsl);
    cudaGetSymbolAddress((void**)&kh,  g_kh);  cudaGetSymbolAddress((void**)&kl,  g_kl);
    cudaGetSymbolAddress((void**)&yh,  g_yh);  cudaGetSymbolAddress((void**)&yl,  g_yl);

    static bool attr_done = false;
    if (!attr_done) {
        cudaFuncSetAttribute(attn_mma,
            cudaFuncAttributeMaxDynamicSharedMemorySize, ATT_SMEM);
        attr_done = true;
    }

    // 0) fused bf16 hi/lo splits of inputs
    split_all<<<(N_X + N_WA + N_WP) / 256, 256>>>(x, w_attn, w_proj);

    // 1) qkv GEMM (epilogue splits q/qs/k/v into bf16 hi/lo buffers)
    gemm_mma<0><<<dim3(QKVn / 128, (Bn * Tn) / 128, 1), 256>>>(
        xh, xl, wah, wal, Cn, Cn, 0, 0, b_attn, sel_w, nullptr);

    // 2) S = relu(scale * qs @ k^T), masked
    gemm_mma<1><<<dim3(Tn / 128, Tn / 128, Bn), 256>>>(
        qsh, qsl, kh, kl, Cn, Cn, (long)Tn * Cn, (long)Tn * Cn,
        nullptr, nullptr, nullptr);

    // 3) FF_shifted = exclusive cumsum of S over rows (triangle-skipped)
    cumsum_p1<<<(Bn * NSEG * Tn) / 256, 256>>>();
    cumsum_p2<<<(Bn * NSEG * Tn) / 256, 256>>>();

    // 4) tensor-core flash attention with forgetting term (BR=64, 2 CTAs/SM)
    attn_mma<<<dim3(Tn / BR, Bn * Hn), 128, ATT_SMEM>>>();

    // 5) out = y @ w_proj^T + b_proj
    gemm_mma<2><<<dim3(Cn / 128, (Bn * Tn) / 128, 1), 256>>>(
        yh, yl, wph, wpl, Cn, Cn, 0, 0, b_proj, nullptr, out);
}